// round 1
// baseline (speedup 1.0000x reference)
#include <cuda_runtime.h>
#include <cuda_bf16.h>
#include <cstdint>

// Problem shapes (fixed by setup_inputs): L=4, B=8, C=256, H=64, W=64
#define L_DIM 4
#define B_DIM 8
#define C_DIM 256
#define SPATIAL 4096            // H*W
#define LBC (L_DIM * B_DIM * C_DIM)   // 8192

// Scratch (allocation-free rule -> __device__ globals)
__device__ float g_gap[LBC];
__device__ float g_attn[LBC];

// ---------------------------------------------------------------------------
// Kernel 1: GAP over spatial dims. One block per (l,b,c); contiguous 16 KB
// slab per block -> perfectly coalesced float4 streaming.
// ---------------------------------------------------------------------------
__global__ __launch_bounds__(256) void gap_kernel(const float* __restrict__ in) {
    const float4* p = reinterpret_cast<const float4*>(in) +
                      (size_t)blockIdx.x * (SPATIAL / 4);
    int t = threadIdx.x;
    float s = 0.f;
#pragma unroll
    for (int i = 0; i < 4; i++) {
        float4 v = p[t + i * 256];
        s += (v.x + v.y) + (v.z + v.w);
    }
#pragma unroll
    for (int o = 16; o; o >>= 1) s += __shfl_xor_sync(0xffffffffu, s, o);

    __shared__ float ws[8];
    if ((t & 31) == 0) ws[t >> 5] = s;
    __syncthreads();
    if (t < 8) {
        float v = ws[t];
#pragma unroll
        for (int o = 4; o; o >>= 1) v += __shfl_xor_sync(0xffu, v, o);
        if (t == 0) g_gap[blockIdx.x] = v * (1.0f / (float)SPATIAL);
    }
}

// ---------------------------------------------------------------------------
// Kernel 2: scores = gap @ W^T, softmax over L. One block per batch b,
// one thread per output channel d. 2 MFLOP total -> latency-bound, tiny.
// ---------------------------------------------------------------------------
__global__ __launch_bounds__(256) void attn_kernel(const float* __restrict__ Wm) {
    __shared__ float gs[L_DIM][C_DIM];
    int b = blockIdx.x;
    int d = threadIdx.x;

#pragma unroll
    for (int l = 0; l < L_DIM; l++)
        gs[l][d] = g_gap[(l * B_DIM + b) * C_DIM + d];
    __syncthreads();

    float sc[L_DIM] = {0.f, 0.f, 0.f, 0.f};
    const float* wrow = Wm + (size_t)d * C_DIM;   // torch Linear: y = x @ W^T
#pragma unroll 8
    for (int c = 0; c < C_DIM; c++) {
        float w = wrow[c];
#pragma unroll
        for (int l = 0; l < L_DIM; l++) sc[l] = fmaf(gs[l][c], w, sc[l]);
    }

    float m = fmaxf(fmaxf(sc[0], sc[1]), fmaxf(sc[2], sc[3]));
    float e[L_DIM], sum = 0.f;
#pragma unroll
    for (int l = 0; l < L_DIM; l++) { e[l] = __expf(sc[l] - m); sum += e[l]; }
    float inv = 1.0f / sum;
#pragma unroll
    for (int l = 0; l < L_DIM; l++)
        g_attn[(l * B_DIM + b) * C_DIM + d] = e[l] * inv;
}

// ---------------------------------------------------------------------------
// Kernel 3: out = in * attn[l,b,c] broadcast over spatial. One block per
// (l,b,c), float4 read+write, fully coalesced.
// ---------------------------------------------------------------------------
__global__ __launch_bounds__(256) void scale_kernel(const float* __restrict__ in,
                                                    float* __restrict__ out) {
    int lbc = blockIdx.x;
    float a = g_attn[lbc];
    size_t base = (size_t)lbc * (SPATIAL / 4);
    const float4* pi = reinterpret_cast<const float4*>(in) + base;
    float4*       po = reinterpret_cast<float4*>(out) + base;
    int t = threadIdx.x;
#pragma unroll
    for (int i = 0; i < 4; i++) {
        float4 v = pi[t + i * 256];
        v.x *= a; v.y *= a; v.z *= a; v.w *= a;
        po[t + i * 256] = v;
    }
}

extern "C" void kernel_launch(void* const* d_in, const int* in_sizes, int n_in,
                              void* d_out, int out_size) {
    const float* in  = (const float*)d_in[0];   // [L,B,C,H,W]
    const float* Wm  = (const float*)d_in[1];   // [C,C]
    float*       out = (float*)d_out;           // [L,B,C,H,W]

    gap_kernel<<<LBC, 256>>>(in);
    attn_kernel<<<B_DIM, 256>>>(Wm);
    scale_kernel<<<LBC, 256>>>(in, out);
}

// round 2
// speedup vs baseline: 1.0250x; 1.0250x over previous
#include <cuda_runtime.h>
#include <cuda_bf16.h>
#include <cstdint>

// Problem shapes (fixed by setup_inputs): L=4, B=8, C=256, H=64, W=64
#define L_DIM 4
#define B_DIM 8
#define C_DIM 256
#define SPATIAL 4096            // H*W
#define LBC (L_DIM * B_DIM * C_DIM)   // 8192

// Scratch (allocation-free rule -> __device__ globals)
__device__ float g_gap[LBC];
__device__ float g_attn[LBC];

// ---------------------------------------------------------------------------
// Kernel 1: GAP over spatial dims. One block per (l,b,c); contiguous 16 KB
// slab per block -> coalesced float4 streaming. Normal (caching) loads so the
// input stays resident in L2 for the second pass.
// ---------------------------------------------------------------------------
__global__ __launch_bounds__(256) void gap_kernel(const float* __restrict__ in) {
    const float4* p = reinterpret_cast<const float4*>(in) +
                      (size_t)blockIdx.x * (SPATIAL / 4);
    int t = threadIdx.x;
    float s = 0.f;
#pragma unroll
    for (int i = 0; i < 4; i++) {
        float4 v = p[t + i * 256];
        s += (v.x + v.y) + (v.z + v.w);
    }
#pragma unroll
    for (int o = 16; o; o >>= 1) s += __shfl_xor_sync(0xffffffffu, s, o);

    __shared__ float ws[8];
    if ((t & 31) == 0) ws[t >> 5] = s;
    __syncthreads();
    if (t < 8) {
        float v = ws[t];
#pragma unroll
        for (int o = 4; o; o >>= 1) v += __shfl_xor_sync(0xffu, v, o);
        if (t == 0) g_gap[blockIdx.x] = v * (1.0f / (float)SPATIAL);
    }
}

// ---------------------------------------------------------------------------
// Kernel 2: scores = gap @ W^T, softmax over L. One block per batch b,
// one thread per output channel d. Tiny.
// ---------------------------------------------------------------------------
__global__ __launch_bounds__(256) void attn_kernel(const float* __restrict__ Wm) {
    __shared__ float gs[L_DIM][C_DIM];
    int b = blockIdx.x;
    int d = threadIdx.x;

#pragma unroll
    for (int l = 0; l < L_DIM; l++)
        gs[l][d] = g_gap[(l * B_DIM + b) * C_DIM + d];
    __syncthreads();

    float sc[L_DIM] = {0.f, 0.f, 0.f, 0.f};
    const float* wrow = Wm + (size_t)d * C_DIM;   // torch Linear: y = x @ W^T
#pragma unroll 8
    for (int c = 0; c < C_DIM; c++) {
        float w = wrow[c];
#pragma unroll
        for (int l = 0; l < L_DIM; l++) sc[l] = fmaf(gs[l][c], w, sc[l]);
    }

    float m = fmaxf(fmaxf(sc[0], sc[1]), fmaxf(sc[2], sc[3]));
    float e[L_DIM], sum = 0.f;
#pragma unroll
    for (int l = 0; l < L_DIM; l++) { e[l] = __expf(sc[l] - m); sum += e[l]; }
    float inv = 1.0f / sum;
#pragma unroll
    for (int l = 0; l < L_DIM; l++)
        g_attn[(l * B_DIM + b) * C_DIM + d] = e[l] * inv;
}

// ---------------------------------------------------------------------------
// Kernel 3: out = in * attn[l,b,c]. Processed in DESCENDING address order so
// the re-read walks the L2-resident MRU tail left behind by gap_kernel
// (ascending order would cascade-evict under LRU and hit DRAM for everything).
// Reads use __ldcs (last use -> evict-first demotion is free); writes use
// __stcs so the output stream does not write-allocate and evict the cached
// input.
// ---------------------------------------------------------------------------
__global__ __launch_bounds__(256) void scale_kernel(const float* __restrict__ in,
                                                    float* __restrict__ out) {
    int lbc = (LBC - 1) - blockIdx.x;          // reverse block order
    float a = g_attn[lbc];
    size_t base = (size_t)lbc * (SPATIAL / 4);
    const float4* pi = reinterpret_cast<const float4*>(in) + base;
    float4*       po = reinterpret_cast<float4*>(out) + base;
    int t = threadIdx.x;
#pragma unroll
    for (int i = 3; i >= 0; i--) {             // descending within block too
        int idx = t + i * 256;
        float4 v = __ldcs(pi + idx);
        v.x *= a; v.y *= a; v.z *= a; v.w *= a;
        __stcs(po + idx, v);
    }
}

extern "C" void kernel_launch(void* const* d_in, const int* in_sizes, int n_in,
                              void* d_out, int out_size) {
    const float* in  = (const float*)d_in[0];   // [L,B,C,H,W]
    const float* Wm  = (const float*)d_in[1];   // [C,C]
    float*       out = (float*)d_out;           // [L,B,C,H,W]

    gap_kernel<<<LBC, 256>>>(in);
    attn_kernel<<<B_DIM, 256>>>(Wm);
    scale_kernel<<<LBC, 256>>>(in, out);
}